// round 14
// baseline (speedup 1.0000x reference)
#include <cuda_runtime.h>
#include <cuda_fp16.h>
#include <math.h>

#define B_ 4
#define S_ 512
#define HID_ 1024
#define NH_ 16
#define DH_ 64

// Scratch (device globals: allocation-free rule)
__device__ __align__(16) float  g_q[B_ * NH_ * S_ * DH_];    // 8 MB [b,h,s,d]
__device__ __align__(16) float  g_k[B_ * NH_ * S_ * DH_];
__device__ __align__(16) float  g_v[B_ * NH_ * S_ * DH_];
__device__ __align__(16) __half g_sch[B_ * NH_ * S_ * S_];   // 32 MB scores -> probs
__device__ __align__(16) float  g_ao[B_ * S_ * HID_];        // 8 MB [b,i,h*64+d]

__device__ __forceinline__ unsigned f2tf(float x) {
    unsigned u;
    asm("cvt.rna.tf32.f32 %0, %1;" : "=r"(u) : "f"(x));
    return u;
}

__device__ __forceinline__ void mma_tf32(float* c, const unsigned* a, const unsigned* b) {
    asm volatile(
        "mma.sync.aligned.m16n8k8.row.col.f32.tf32.tf32.f32 "
        "{%0,%1,%2,%3}, {%4,%5,%6,%7}, {%8,%9}, {%0,%1,%2,%3};"
        : "+f"(c[0]), "+f"(c[1]), "+f"(c[2]), "+f"(c[3])
        : "r"(a[0]), "r"(a[1]), "r"(a[2]), "r"(a[3]), "r"(b[0]), "r"(b[1]));
}

__device__ __forceinline__ unsigned sptr(const void* p) {
    return (unsigned)__cvta_generic_to_shared(p);
}
__device__ __forceinline__ void cpa16(void* dst, const void* src) {
    asm volatile("cp.async.cg.shared.global [%0], [%1], 16;" :: "r"(sptr(dst)), "l"(src));
}
#define CP_COMMIT() asm volatile("cp.async.commit_group;")
#define CP_WAIT(n)  asm volatile("cp.async.wait_group %0;" :: "n"(n))

// ---------------------------------------------------------------------------
// TF32 tensor-core GEMM body. cp.async ring of NSTAGE buffers.
// AHALF: A operand fp16 in gmem (vectorized repack; the fp16-B path is
// intentionally ABSENT — measured toxic in R11/R12).
// OUTMODE 0: f32 C[row*N+col]+z*sC. 1: f32 head-split scatter.
//         2: AO accumulate f32. 3: half C[row*N+col]+z*sC.
// ---------------------------------------------------------------------------
template<int BN, int BNN, int OUTMODE, int AHALF, int NSTAGE>
__device__ __forceinline__ void gemm_body(
    const void* __restrict__ Ab_, const float* __restrict__ Bb,
    const float* __restrict__ bias, void* __restrict__ C_,
    int N, int K, int z, long sC, unsigned* smem_u)
{
    constexpr int NT8 = BN / 8;
    constexpr int NTW = NT8 / 4;
    constexpr int APACK = 4224;
    constexpr int BPACK = ((((NT8 * 4 - 1) * 33) + 31) * 2 + 2 + 3) & ~3;
    constexpr int RA_BYTES = AHALF ? (128 * 40 * 2) : (128 * 36 * 4);
    constexpr int RB_BYTES = (BNN == 0) ? BN * 36 * 4 : 32 * (BN + 4) * 4;

    unsigned* sA_ = smem_u;
    unsigned* sB_ = smem_u + APACK;
    char* rawA = (char*)(smem_u + APACK + BPACK);
    char* rawB = rawA + NSTAGE * RA_BYTES;

    const int m0 = blockIdx.y * 128;
    const int n0 = blockIdx.x * BN;
    const int tid = threadIdx.x;
    const int lane = tid & 31;
    const int wid = tid >> 5;
    const int wm = wid & 1;
    const int wn = wid >> 1;

    const float*  Abf = (const float*)Ab_;
    const __half* Abh = (const __half*)Ab_;

    float acc[4][NTW][4];
#pragma unroll
    for (int mt = 0; mt < 4; mt++)
#pragma unroll
        for (int nt = 0; nt < NTW; nt++)
#pragma unroll
            for (int e = 0; e < 4; e++) acc[mt][nt][e] = 0.f;

    const int nTiles = K >> 5;

    auto loadA = [&](int kt, char* dstA) {
        if (AHALF == 0) {
            float* dA = (float*)dstA;
#pragma unroll
            for (int i = 0; i < 4; i++) {
                int f = tid + i * 256;
                int row = f >> 3, k4 = (f & 7) * 4;
                cpa16(&dA[row * 36 + k4], &Abf[(long)(m0 + row) * K + kt + k4]);
            }
        } else {
            __half* dA = (__half*)dstA;
#pragma unroll
            for (int i = 0; i < 2; i++) {
                int f = tid + i * 256;
                int row = f >> 2, k8 = (f & 3) * 8;
                cpa16(&dA[row * 40 + k8], &Abh[(long)(m0 + row) * K + kt + k8]);
            }
        }
    };
    auto loadB = [&](int kt, char* dstB) {
        float* dB = (float*)dstB;
        if (BNN == 0) {
#pragma unroll
            for (int i = 0; i < BN / 32; i++) {
                int f = tid + i * 256;
                int n = f >> 3, k4 = (f & 7) * 4;
                cpa16(&dB[n * 36 + k4], &Bb[(long)(n0 + n) * K + kt + k4]);
            }
        } else {
#pragma unroll
            for (int i = 0; i < BN / 32; i++) {
                int f = tid + i * 256;
                int k = f / (BN / 4), n4 = (f % (BN / 4)) * 4;
                cpa16(&dB[k * (BN + 4) + n4], &Bb[(long)(kt + k) * N + n0 + n4]);
            }
        }
    };

    // ---- preload stages 0..NSTAGE-2 ----
#pragma unroll
    for (int s = 0; s < NSTAGE - 1; s++) {
        if (s < nTiles) {
            loadA(s * 32, rawA + s * RA_BYTES);
            loadB(s * 32, rawB + s * RB_BYTES);
        }
        CP_COMMIT();
    }

    for (int t = 0; t < nTiles; t++) {
        CP_WAIT(NSTAGE - 2);
        __syncthreads();

        {
            int nx = t + NSTAGE - 1;
            if (nx < nTiles) {
                loadA(nx * 32, rawA + (nx % NSTAGE) * RA_BYTES);
                loadB(nx * 32, rawB + (nx % NSTAGE) * RB_BYTES);
            }
            CP_COMMIT();
        }

        const int cur = t % NSTAGE;

        // ---- repack A ----
        if (AHALF == 0) {
            const float* rA = (const float*)(rawA + cur * RA_BYTES);
#pragma unroll
            for (int i = 0; i < 4; i++) {
                int f = tid + i * 256;
                int row = f >> 3;
                int k4 = (f & 7) * 4;
                float4 v = *(const float4*)&rA[row * 36 + k4];
                int ks = k4 >> 3;
                int mt = row >> 4, rr = row & 15;
                int regb = ((k4 & 4) ? 2 : 0) + (rr >= 8 ? 1 : 0);
                unsigned* p = &sA_[(((mt * 4 + ks) * 33) + (rr & 7) * 4) * 4 + regb];
                p[0] = f2tf(v.x); p[4] = f2tf(v.y); p[8] = f2tf(v.z); p[12] = f2tf(v.w);
            }
        } else {
            const __half* rA = (const __half*)(rawA + cur * RA_BYTES);
#pragma unroll
            for (int i = 0; i < 2; i++) {
                int f = tid + i * 256;
                int row = f >> 2;
                int k8 = (f & 3) * 8;
                const __half2* hv = (const __half2*)&rA[row * 40 + k8];
                float2 f0 = __half22float2(hv[0]);
                float2 f1 = __half22float2(hv[1]);
                float2 f2 = __half22float2(hv[2]);
                float2 f3 = __half22float2(hv[3]);
                int ks = k8 >> 3;
                int mt = row >> 4, rr = row & 15;
                int rb8 = (rr >= 8 ? 1 : 0);
                unsigned* p = &sA_[(((mt * 4 + ks) * 33) + (rr & 7) * 4) * 4];
                p[rb8 + 0]  = f2tf(f0.x); p[rb8 + 4]  = f2tf(f0.y);
                p[rb8 + 8]  = f2tf(f1.x); p[rb8 + 12] = f2tf(f1.y);
                p[rb8 + 2]  = f2tf(f2.x); p[rb8 + 6]  = f2tf(f2.y);
                p[rb8 + 10] = f2tf(f3.x); p[rb8 + 14] = f2tf(f3.y);
            }
        }
        // ---- repack B (f32 only) ----
        {
            const float* rB = (const float*)(rawB + cur * RB_BYTES);
            if (BNN == 0) {
#pragma unroll
                for (int i = 0; i < BN / 32; i++) {
                    int f = tid + i * 256;
                    int n = f >> 3;
                    int k4 = (f & 7) * 4;
                    float4 v = *(const float4*)&rB[n * 36 + k4];
                    int ks = k4 >> 3;
                    int reg = (k4 & 4) ? 1 : 0;
                    int nt = n >> 3;
                    unsigned* p = &sB_[(((nt * 4 + ks) * 33) + (n & 7) * 4) * 2 + reg];
                    p[0] = f2tf(v.x); p[2] = f2tf(v.y); p[4] = f2tf(v.z); p[6] = f2tf(v.w);
                }
            } else {
#pragma unroll
                for (int i = 0; i < BN / 32; i++) {
                    int f = tid + i * 256;
                    int k = f / (BN / 4);
                    int n4 = (f % (BN / 4)) * 4;
                    float4 v = *(const float4*)&rB[k * (BN + 4) + n4];
                    int ks = k >> 3, kc = k & 7;
                    int reg = (kc & 4) ? 1 : 0;
                    int nt = n4 >> 3;
                    unsigned* p = &sB_[(((nt * 4 + ks) * 33) + (n4 & 7) * 4 + (kc & 3)) * 2 + reg];
                    p[0] = f2tf(v.x); p[8] = f2tf(v.y); p[16] = f2tf(v.z); p[24] = f2tf(v.w);
                }
            }
        }
        __syncthreads();

        // ---- compute ----
#pragma unroll
        for (int ks = 0; ks < 4; ks++) {
            unsigned af[4][4];
            unsigned bf[NTW][2];
#pragma unroll
            for (int mt = 0; mt < 4; mt++) {
                uint4 tt = *(const uint4*)&sA_[((((wm * 4 + mt) * 4 + ks) * 33) + lane) * 4];
                af[mt][0] = tt.x; af[mt][1] = tt.y; af[mt][2] = tt.z; af[mt][3] = tt.w;
            }
#pragma unroll
            for (int nt = 0; nt < NTW; nt++) {
                uint2 tt = *(const uint2*)&sB_[((((wn * NTW + nt) * 4 + ks) * 33) + lane) * 2];
                bf[nt][0] = tt.x; bf[nt][1] = tt.y;
            }
#pragma unroll
            for (int mt = 0; mt < 4; mt++)
#pragma unroll
                for (int nt = 0; nt < NTW; nt++)
                    mma_tf32(acc[mt][nt], af[mt], bf[nt]);
        }
    }

    // ---- epilogue ----
    const int r0 = lane >> 2;
    const int c0l = (lane & 3) * 2;
#pragma unroll
    for (int mt = 0; mt < 4; mt++) {
#pragma unroll
        for (int nt = 0; nt < NTW; nt++) {
            int row = m0 + wm * 64 + mt * 16 + r0;
            int col = n0 + (wn * NTW + nt) * 8 + c0l;
            float2 v0 = make_float2(acc[mt][nt][0], acc[mt][nt][1]);
            float2 v1 = make_float2(acc[mt][nt][2], acc[mt][nt][3]);
            if (bias) {
                float bx = bias[col], by = bias[col + 1];
                v0.x += bx; v0.y += by;
                v1.x += bx; v1.y += by;
            }
            if (OUTMODE == 0) {
                float* Cb = (float*)C_ + (long)z * sC;
                *(float2*)&Cb[(long)row * N + col] = v0;
                *(float2*)&Cb[(long)(row + 8) * N + col] = v1;
            } else if (OUTMODE == 1) {
                float* C = (float*)C_;
                int bb = row >> 9, s = row & 511, h = col >> 6, d = col & 63;
                *(float2*)&C[(((long)(bb * NH_ + h)) * S_ + s) * DH_ + d] = v0;
                *(float2*)&C[(((long)(bb * NH_ + h)) * S_ + s + 8) * DH_ + d] = v1;
            } else if (OUTMODE == 2) {
                float* C = (float*)C_;
                int b = z >> 4, h = z & 15;
                float* base = C + ((long)(b * S_ + row)) * HID_ + h * 64 + col;
                float2 o0 = *(float2*)base;
                float2 o1 = *(float2*)(base + 8 * HID_);
                o0.x += v0.x; o0.y += v0.y;
                o1.x += v1.x; o1.y += v1.y;
                *(float2*)base = o0;
                *(float2*)(base + 8 * HID_) = o1;
            } else {
                __half* Cb = (__half*)C_ + (long)z * sC;
                *(__half2*)&Cb[(long)row * N + col] = __floats2half2_rn(v0.x, v0.y);
                *(__half2*)&Cb[(long)(row + 8) * N + col] = __floats2half2_rn(v1.x, v1.y);
            }
        }
    }
}

// ---- generic single-GEMM wrapper ----
template<int BN, int BNN, int OUTMODE, int AHALF, int NSTAGE>
__global__ __launch_bounds__(256, 2) void mma_gemm(
    const void* __restrict__ A, const float* __restrict__ Bm,
    const float* __restrict__ bias, void* __restrict__ C,
    int N, int K, long sA, long sB, long sC)
{
    extern __shared__ unsigned smem_u[];
    const int z = blockIdx.z;
    const void* Az = AHALF ? (const void*)((const __half*)A + (long)z * sA)
                           : (const void*)((const float*)A + (long)z * sA);
    gemm_body<BN, BNN, OUTMODE, AHALF, NSTAGE>(Az, Bm + (long)z * sB, bias, C,
                                               N, K, z, sC, smem_u);
}

// ---- merged QKV projection (f32 in/out, head-split) — exact R9 config ----
struct QKVArgs {
    const float* A[3];
    const float* W[3];
    const float* b[3];
    float* C[3];
};
__global__ __launch_bounds__(256, 2) void qkv_gemm(QKVArgs p)
{
    extern __shared__ unsigned smem_u[];
    const int z = blockIdx.z;
    gemm_body<128, 0, 1, 0, 2>(p.A[z], p.W[z], p.b[z], p.C[z],
                               HID_, HID_, z, 0, smem_u);
}

// smem byte sizes
#define GSM_128 ((4224 + 4224) * 4 + 2 * (128 * 36 * 4 + 128 * 36 * 4))   // 107520
#define GSM_O   ((4224 + 2112) * 4 + 2 * (128 * 36 * 4 + 64 * 36 * 4))    // 80640
#define GSM_PV  ((4224 + 2112) * 4 + 4 * (128 * 40 * 2 + 32 * 68 * 4))    // 101120

// ---------------------------------------------------------------------------
// Fused rel kernel, streaming-softmax — byte-identical to the 348us version.
// Scores staged fp16 (converted at the exp), probs written back fp16.
// ---------------------------------------------------------------------------
#define RELP 72
#define SCP  516
#define CHUNK_F (64 * RELP)
#define SMEM_F ((16 * SCP + 16 * RELP + 1024 + 3 * CHUNK_F + 128 + 16 + 4096) * 4)

__global__ __launch_bounds__(256, 2) void rel_fused(
    const float* __restrict__ q, const float* __restrict__ rel,
    const float* __restrict__ Kp, __half* __restrict__ sc,
    float* __restrict__ AO)
{
    extern __shared__ float sm[];
    float* s_sc  = sm;                          // 16 x 516 (e values)
    float* s_qk  = sm + 16 * SCP;               // 16 x 72
    float* s_kp  = s_qk + 16 * RELP;            // 1024
    float* s_rel = s_kp + 1024;                 // 3 x 64 x 72 ring
    float* s_red = s_rel + 3 * CHUNK_F;         // 8 x 16
    float* s_inv = s_red + 128;                 // 16
    __half* s_sch = (__half*)(s_inv + 16);      // 16 x 512 scores (fp16)

    const int bi = blockIdx.x;
    const int b = bi >> 9, i = bi & 511;
    const int tid = threadIdx.x;
    const int lane = tid & 31;
    const int wid = tid >> 5;
    const int lg = lane >> 2;
    const int lm = lane & 3;

    const float* relb = rel + ((long)b * S_ * S_ + i) * DH_;
    __half* scb = sc + (((long)(b * NH_)) * S_ + i) * S_;   // + h*S_*S_ + j

    // ---- stage scores (fp16), Kp, q row ----
#pragma unroll
    for (int qq = 0; qq < 4; qq++) {
        int f = tid + qq * 256;
        int h = f >> 6, jv8 = (f & 63) * 8;
        cpa16(&s_sch[h * 512 + jv8], scb + (long)h * (S_ * S_) + jv8);
    }
    cpa16(&s_kp[tid * 4], Kp + tid * 4);
    {
        int h = tid >> 4, c4 = (tid & 15) * 4;
        cpa16(&s_qk[h * RELP + c4],
              q + (((long)(b * NH_ + h)) * S_ + i) * DH_ + c4);
    }
    CP_COMMIT();

    // ---- prime ring: chunks 0,1 ----
#pragma unroll
    for (int c = 0; c < 2; c++) {
#pragma unroll
        for (int qq = 0; qq < 4; qq++) {
            int f = tid + qq * 256;
            int r = f >> 4, c4 = (f & 15) * 4;
            cpa16(&s_rel[c * CHUNK_F + r * RELP + c4],
                  relb + (long)(c * 64 + r) * (S_ * DH_) + c4);
        }
        CP_COMMIT();
    }

    CP_WAIT(2);
    __syncthreads();
    for (int idx = tid; idx < 1024; idx += 256)
        s_qk[(idx >> 6) * RELP + (idx & 63)] *= s_kp[idx];
    __syncthreads();

    unsigned af[8][4];
#pragma unroll
    for (int ks = 0; ks < 8; ks++) {
        af[ks][0] = f2tf(s_qk[lg * RELP + ks * 8 + lm]);
        af[ks][1] = f2tf(s_qk[(lg + 8) * RELP + ks * 8 + lm]);
        af[ks][2] = f2tf(s_qk[lg * RELP + ks * 8 + 4 + lm]);
        af[ks][3] = f2tf(s_qk[(lg + 8) * RELP + ks * 8 + 4 + lm]);
    }

    float acc2[4] = {0.f, 0.f, 0.f, 0.f};
    float psum_lo = 0.f, psum_hi = 0.f;
    const int d0 = wid * 8;

#pragma unroll
    for (int t = 0; t < 8; t++) {
        if (t < 7) { CP_WAIT(1); } else { CP_WAIT(0); }
        __syncthreads();
        if (t + 2 < 8) {
            int c = t + 2;
            float* dst = s_rel + (c % 3) * CHUNK_F;
#pragma unroll
            for (int qq = 0; qq < 4; qq++) {
                int f = tid + qq * 256;
                int r = f >> 4, c4 = (f & 15) * 4;
                cpa16(&dst[r * RELP + c4],
                      relb + (long)(c * 64 + r) * (S_ * DH_) + c4);
            }
            CP_COMMIT();
        }

        const float* rb_base = s_rel + (t % 3) * CHUNK_F;

        // ---- mma1 ----
        float acc[4] = {0.f, 0.f, 0.f, 0.f};
        const float* rb = rb_base + (wid * 8 + lg) * RELP;
#pragma unroll
        for (int ks = 0; ks < 8; ks++) {
            unsigned bf[2];
            bf[0] = f2tf(rb[ks * 8 + lm]);
            bf[1] = f2tf(rb[ks * 8 + 4 + lm]);
            mma_tf32(acc, af[ks], bf);
        }

        // ---- e-phase (score base from fp16 staging) ----
        {
            int col = t * 64 + wid * 8 + lm * 2;
            float b00 = __half2float(s_sch[lg * 512 + col]);
            float b01 = __half2float(s_sch[lg * 512 + col + 1]);
            float b10 = __half2float(s_sch[(lg + 8) * 512 + col]);
            float b11 = __half2float(s_sch[(lg + 8) * 512 + col + 1]);
            float e00 = __expf((b00 + acc[0]) * 0.125f);
            float e01 = __expf((b01 + acc[1]) * 0.125f);
            float e10 = __expf((b10 + acc[2]) * 0.125f);
            float e11 = __expf((b11 + acc[3]) * 0.125f);
            s_sc[lg * SCP + col]           = e00;
            s_sc[lg * SCP + col + 1]       = e01;
            s_sc[(lg + 8) * SCP + col]     = e10;
            s_sc[(lg + 8) * SCP + col + 1] = e11;
            psum_lo += e00 + e01;
            psum_hi += e10 + e11;
        }
        __syncthreads();

        // ---- mma2 ----
#pragma unroll
        for (int ks = 0; ks < 8; ks++) {
            unsigned a2f[4], b2f[2];
            a2f[0] = f2tf(s_sc[lg * SCP + t * 64 + ks * 8 + lm]);
            a2f[1] = f2tf(s_sc[(lg + 8) * SCP + t * 64 + ks * 8 + lm]);
            a2f[2] = f2tf(s_sc[lg * SCP + t * 64 + ks * 8 + 4 + lm]);
            a2f[3] = f2tf(s_sc[(lg + 8) * SCP + t * 64 + ks * 8 + 4 + lm]);
            b2f[0] = f2tf(rb_base[(ks * 8 + lm) * RELP + d0 + lg]);
            b2f[1] = f2tf(rb_base[(ks * 8 + 4 + lm) * RELP + d0 + lg]);
            mma_tf32(acc2, a2f, b2f);
        }
    }

    psum_lo += __shfl_xor_sync(0xffffffffu, psum_lo, 1);
    psum_lo += __shfl_xor_sync(0xffffffffu, psum_lo, 2);
    psum_hi += __shfl_xor_sync(0xffffffffu, psum_hi, 1);
    psum_hi += __shfl_xor_sync(0xffffffffu, psum_hi, 2);
    if (lm == 0) {
        s_red[wid * 16 + lg]     = psum_lo;
        s_red[wid * 16 + 8 + lg] = psum_hi;
    }
    __syncthreads();
    if (tid < 16) {
        float s = 0.f;
#pragma unroll
        for (int w = 0; w < 8; w++) s += s_red[w * 16 + tid];
        s_inv[tid] = 1.0f / s;
    }
    __syncthreads();

    // ---- probs writeback (normalized, fp16) ----
#pragma unroll
    for (int qq = 0; qq < 8; qq++) {
        int idx = tid + qq * 256;
        int h = idx >> 7, jv = idx & 127;
        float inv = s_inv[h];
        float4 v = *(const float4*)&s_sc[h * SCP + jv * 4];
        __half2 lo = __floats2half2_rn(v.x * inv, v.y * inv);
        __half2 hi = __floats2half2_rn(v.z * inv, v.w * inv);
        uint2 u;
        u.x = *(unsigned*)&lo;
        u.y = *(unsigned*)&hi;
        *(uint2*)(scb + (long)h * (S_ * S_) + jv * 4) = u;
    }

    // ---- AO = Kp * racc * inv ----
    {
        float i_lo = s_inv[lg], i_hi = s_inv[lg + 8];
        const int dcol = d0 + lm * 2;
        const long obase = ((long)(b * S_ + i)) * HID_;
        float2 o0, o1;
        o0.x = s_kp[lg * 64 + dcol]           * acc2[0] * i_lo;
        o0.y = s_kp[lg * 64 + dcol + 1]       * acc2[1] * i_lo;
        o1.x = s_kp[(lg + 8) * 64 + dcol]     * acc2[2] * i_hi;
        o1.y = s_kp[(lg + 8) * 64 + dcol + 1] * acc2[3] * i_hi;
        *(float2*)&AO[obase + lg * 64 + dcol] = o0;
        *(float2*)&AO[obase + (lg + 8) * 64 + dcol] = o1;
    }
}

// ---------------------------------------------------------------------------
extern "C" void kernel_launch(void* const* d_in, const int* in_sizes, int n_in,
                              void* d_out, int out_size)
{
    const float* key   = (const float*)d_in[0];
    const float* value = (const float*)d_in[1];
    const float* query = (const float*)d_in[2];
    const float* rel   = (const float*)d_in[3];
    const float* Wq = (const float*)d_in[5];
    const float* bq = (const float*)d_in[6];
    const float* Wk = (const float*)d_in[7];
    const float* bk = (const float*)d_in[8];
    const float* Wv = (const float*)d_in[9];
    const float* bv = (const float*)d_in[10];
    const float* Kp = (const float*)d_in[11];
    const float* Wo = (const float*)d_in[12];
    const float* bo = (const float*)d_in[13];
    float* out = (float*)d_out;

    float *q_, *k_, *v_, *ao_;
    __half* sch_;
    cudaGetSymbolAddress((void**)&q_, g_q);
    cudaGetSymbolAddress((void**)&k_, g_k);
    cudaGetSymbolAddress((void**)&v_, g_v);
    cudaGetSymbolAddress((void**)&sch_, g_sch);
    cudaGetSymbolAddress((void**)&ao_, g_ao);

    cudaFuncSetAttribute(rel_fused, cudaFuncAttributeMaxDynamicSharedMemorySize, SMEM_F);
    cudaFuncSetAttribute(qkv_gemm, cudaFuncAttributeMaxDynamicSharedMemorySize, GSM_128);
    cudaFuncSetAttribute(mma_gemm<128, 0, 3, 0, 2>, cudaFuncAttributeMaxDynamicSharedMemorySize, GSM_128);
    cudaFuncSetAttribute(mma_gemm<64, 1, 2, 1, 4>,  cudaFuncAttributeMaxDynamicSharedMemorySize, GSM_PV);
    cudaFuncSetAttribute(mma_gemm<64, 0, 0, 0, 2>,  cudaFuncAttributeMaxDynamicSharedMemorySize, GSM_O);

    dim3 thr(256);

    // 1) q/k/v projections, merged (grid.z = 3), f32 — exact R9 config
    QKVArgs qa;
    qa.A[0] = query; qa.A[1] = key; qa.A[2] = value;
    qa.W[0] = Wq;    qa.W[1] = Wk;  qa.W[2] = Wv;
    qa.b[0] = bq;    qa.b[1] = bk;  qa.b[2] = bv;
    qa.C[0] = q_;    qa.C[1] = k_;  qa.C[2] = v_;
    qkv_gemm<<<dim3(8, 16, 3), thr, GSM_128>>>(qa);

    // 2) scores = q @ k^T (f32 operands, fp16 out) — exact R9 config
    mma_gemm<128, 0, 3, 0, 2><<<dim3(4, 4, 64), thr, GSM_128>>>(
        q_, k_, nullptr, sch_, S_, DH_,
        (long)S_ * DH_, (long)S_ * DH_, (long)S_ * S_);

    // 3) fused rel/softmax — exact R9 kernel
    rel_fused<<<B_ * S_, thr, SMEM_F>>>(q_, rel, Kp, sch_, ao_);

    // 4) AO += probs(fp16) @ v(f32) — R9 config EXCEPT ring depth 2 -> 4
    mma_gemm<64, 1, 2, 1, 4><<<dim3(1, 4, 64), thr, GSM_PV>>>(
        sch_, v_, nullptr, ao_, DH_, S_,
        (long)S_ * S_, (long)S_ * DH_, 0);

    // 5) final projection — exact R9 config
    mma_gemm<64, 0, 0, 0, 2><<<dim3(16, 16, 1), thr, GSM_O>>>(
        ao_, Wo, bo, out, HID_, HID_, 0, 0, 0);
}

// round 16
// speedup vs baseline: 1.2038x; 1.2038x over previous
#include <cuda_runtime.h>
#include <cuda_fp16.h>
#include <math.h>

#define B_ 4
#define S_ 512
#define HID_ 1024
#define NH_ 16
#define DH_ 64

// Scratch (device globals: allocation-free rule)
__device__ __align__(16) __half g_inh[3 * B_ * S_ * HID_];   // fp16 inputs
__device__ __align__(16) __half g_wh[3 * HID_ * HID_];       // fp16 Wq,Wk,Wv
__device__ __align__(16) __half g_qh[B_ * NH_ * S_ * DH_];   // fp16 q [b,h,s,d]
__device__ __align__(16) __half g_kh[B_ * NH_ * S_ * DH_];   // fp16 k
__device__ __align__(16) float  g_v[B_ * NH_ * S_ * DH_];    // f32 v (PV B operand)
__device__ __align__(16) __half g_sch[B_ * NH_ * S_ * S_];   // scores -> probs
__device__ __align__(16) float  g_ao[B_ * S_ * HID_];        // [b,i,h*64+d]

__device__ __forceinline__ unsigned f2tf(float x) {
    unsigned u;
    asm("cvt.rna.tf32.f32 %0, %1;" : "=r"(u) : "f"(x));
    return u;
}

__device__ __forceinline__ void mma_tf32(float* c, const unsigned* a, const unsigned* b) {
    asm volatile(
        "mma.sync.aligned.m16n8k8.row.col.f32.tf32.tf32.f32 "
        "{%0,%1,%2,%3}, {%4,%5,%6,%7}, {%8,%9}, {%0,%1,%2,%3};"
        : "+f"(c[0]), "+f"(c[1]), "+f"(c[2]), "+f"(c[3])
        : "r"(a[0]), "r"(a[1]), "r"(a[2]), "r"(a[3]), "r"(b[0]), "r"(b[1]));
}

__device__ __forceinline__ void mma_f16(float* c, const unsigned* a, const unsigned* b) {
    asm volatile(
        "mma.sync.aligned.m16n8k16.row.col.f32.f16.f16.f32 "
        "{%0,%1,%2,%3}, {%4,%5,%6,%7}, {%8,%9}, {%0,%1,%2,%3};"
        : "+f"(c[0]), "+f"(c[1]), "+f"(c[2]), "+f"(c[3])
        : "r"(a[0]), "r"(a[1]), "r"(a[2]), "r"(a[3]), "r"(b[0]), "r"(b[1]));
}

__device__ __forceinline__ unsigned sptr(const void* p) {
    return (unsigned)__cvta_generic_to_shared(p);
}
__device__ __forceinline__ void cpa16(void* dst, const void* src) {
    asm volatile("cp.async.cg.shared.global [%0], [%1], 16;" :: "r"(sptr(dst)), "l"(src));
}
#define CP_COMMIT() asm volatile("cp.async.commit_group;")
#define CP_WAIT(n)  asm volatile("cp.async.wait_group %0;" :: "n"(n))

// ---------------------------------------------------------------------------
// f32 -> fp16 bulk convert: 6 segments (3 inputs, 3 weights)
// ---------------------------------------------------------------------------
struct CvtArgs {
    const float* s[6];
    __half* d[6];
    int n4[6];
};
__global__ __launch_bounds__(256) void cvt_f2h(CvtArgs a)
{
#pragma unroll
    for (int seg = 0; seg < 6; seg++) {
        const float4* s4 = (const float4*)a.s[seg];
        __half2* d2 = (__half2*)a.d[seg];
        int n4 = a.n4[seg];
        for (int i = blockIdx.x * blockDim.x + threadIdx.x; i < n4;
             i += gridDim.x * blockDim.x) {
            float4 v = s4[i];
            d2[i * 2]     = __floats2half2_rn(v.x, v.y);
            d2[i * 2 + 1] = __floats2half2_rn(v.z, v.w);
        }
    }
}

// ---------------------------------------------------------------------------
// Native fp16 HMMA GEMM body (m16n8k16). NT only: A [M,K], B [N,K], both fp16.
// BM=128, BK=32 (2 k-steps of 16), cp.async ring of NSTAGE.
// APACK = 8 mt * 2 ksteps * 33 * 4 = 2112 u32  (R15 bug: was 1056 -> overflow)
// OUTMODE 1: f32 head-split scatter. 3: half C[row*N+col]+z*sC.
//         4: half head-split scatter.
// ---------------------------------------------------------------------------
template<int BN, int OUTMODE, int NSTAGE>
__device__ __forceinline__ void hgemm_body(
    const __half* __restrict__ Ab, const __half* __restrict__ Bb,
    const float* __restrict__ bias, void* __restrict__ C_,
    int N, int K, int z, long sC, unsigned* smem_u)
{
    constexpr int NT8 = BN / 8;
    constexpr int NTW = NT8 / 4;
    constexpr int APACK = 2112;                       // u32 (FIXED)
    constexpr int BPACK = (BN == 128) ? 2112 : 1056;  // u32
    constexpr int RA_H = 128 * 40;                    // halves / stage
    constexpr int RB_H = BN * 40;

    unsigned* sA_ = smem_u;
    unsigned* sB_ = smem_u + APACK;
    __half* rawA = (__half*)(smem_u + APACK + BPACK);
    __half* rawB = rawA + NSTAGE * RA_H;

    const int m0 = blockIdx.y * 128;
    const int n0 = blockIdx.x * BN;
    const int tid = threadIdx.x;
    const int lane = tid & 31;
    const int wid = tid >> 5;
    const int wm = wid & 1;
    const int wn = wid >> 1;

    float acc[4][NTW][4];
#pragma unroll
    for (int mt = 0; mt < 4; mt++)
#pragma unroll
        for (int nt = 0; nt < NTW; nt++)
#pragma unroll
            for (int e = 0; e < 4; e++) acc[mt][nt][e] = 0.f;

    const int nTiles = K >> 5;

    auto loadA = [&](int kt, __half* dA) {
#pragma unroll
        for (int i = 0; i < 2; i++) {
            int f = tid + i * 256;
            int row = f >> 2, k8 = (f & 3) * 8;
            cpa16(&dA[row * 40 + k8], &Ab[(long)(m0 + row) * K + kt + k8]);
        }
    };
    auto loadB = [&](int kt, __half* dB) {
#pragma unroll
        for (int i = 0; i < BN / 64; i++) {
            int f = tid + i * 256;
            int n = f >> 2, k8 = (f & 3) * 8;
            cpa16(&dB[n * 40 + k8], &Bb[(long)(n0 + n) * K + kt + k8]);
        }
    };

    // ---- preload stages 0..NSTAGE-2 ----
#pragma unroll
    for (int s = 0; s < NSTAGE - 1; s++) {
        if (s < nTiles) {
            loadA(s * 32, rawA + s * RA_H);
            loadB(s * 32, rawB + s * RB_H);
        }
        CP_COMMIT();
    }

    for (int t = 0; t < nTiles; t++) {
        CP_WAIT(NSTAGE - 2);
        __syncthreads();

        {
            int nx = t + NSTAGE - 1;
            if (nx < nTiles) {
                loadA(nx * 32, rawA + (nx % NSTAGE) * RA_H);
                loadB(nx * 32, rawB + (nx % NSTAGE) * RB_H);
            }
            CP_COMMIT();
        }

        const int cur = t % NSTAGE;

        // ---- repack A: raw fp16 -> packed m16n8k16 fragments ----
        {
            const __half* rA = rawA + cur * RA_H;
#pragma unroll
            for (int i = 0; i < 2; i++) {
                int f = tid + i * 256;
                int row = f >> 2;
                int k8 = (f & 3) * 8;
                uint4 hv = *(const uint4*)&rA[row * 40 + k8];
                int kstep = k8 >> 4;
                int hi = (k8 >> 3) & 1;
                int mt = row >> 4, rr = row & 15;
                int regb = hi * 2 + (rr >= 8 ? 1 : 0);
                unsigned* p = &sA_[(((mt * 2 + kstep) * 33) + (rr & 7) * 4) * 4 + regb];
                p[0] = hv.x; p[4] = hv.y; p[8] = hv.z; p[12] = hv.w;
            }
        }
        // ---- repack B ----
        {
            const __half* rB = rawB + cur * RB_H;
#pragma unroll
            for (int i = 0; i < BN / 64; i++) {
                int f = tid + i * 256;
                int n = f >> 2;
                int k8 = (f & 3) * 8;
                uint4 hv = *(const uint4*)&rB[n * 40 + k8];
                int kstep = k8 >> 4;
                int hi = (k8 >> 3) & 1;
                int nt = n >> 3;
                unsigned* p = &sB_[(((nt * 2 + kstep) * 33) + (n & 7) * 4) * 2 + hi];
                p[0] = hv.x; p[2] = hv.y; p[4] = hv.z; p[6] = hv.w;
            }
        }
        __syncthreads();

        // ---- compute: 2 k-steps of m16n8k16 ----
#pragma unroll
        for (int ks = 0; ks < 2; ks++) {
            unsigned af[4][4];
            unsigned bf[NTW][2];
#pragma unroll
            for (int mt = 0; mt < 4; mt++) {
                uint4 tt = *(const uint4*)&sA_[((((wm * 4 + mt) * 2 + ks) * 33) + lane) * 4];
                af[mt][0] = tt.x; af[mt][1] = tt.y; af[mt][2] = tt.z; af[mt][3] = tt.w;
            }
#pragma unroll
            for (int nt = 0; nt < NTW; nt++) {
                uint2 tt = *(const uint2*)&sB_[((((wn * NTW + nt) * 2 + ks) * 33) + lane) * 2];
                bf[nt][0] = tt.x; bf[nt][1] = tt.y;
            }
#pragma unroll
            for (int mt = 0; mt < 4; mt++)
#pragma unroll
                for (int nt = 0; nt < NTW; nt++)
                    mma_f16(acc[mt][nt], af[mt], bf[nt]);
        }
    }

    // ---- epilogue ----
    const int r0 = lane >> 2;
    const int c0l = (lane & 3) * 2;
#pragma unroll
    for (int mt = 0; mt < 4; mt++) {
#pragma unroll
        for (int nt = 0; nt < NTW; nt++) {
            int row = m0 + wm * 64 + mt * 16 + r0;
            int col = n0 + (wn * NTW + nt) * 8 + c0l;
            float2 v0 = make_float2(acc[mt][nt][0], acc[mt][nt][1]);
            float2 v1 = make_float2(acc[mt][nt][2], acc[mt][nt][3]);
            if (bias) {
                float bx = bias[col], by = bias[col + 1];
                v0.x += bx; v0.y += by;
                v1.x += bx; v1.y += by;
            }
            if (OUTMODE == 1) {
                float* C = (float*)C_;
                int bb = row >> 9, s = row & 511, h = col >> 6, d = col & 63;
                *(float2*)&C[(((long)(bb * NH_ + h)) * S_ + s) * DH_ + d] = v0;
                *(float2*)&C[(((long)(bb * NH_ + h)) * S_ + s + 8) * DH_ + d] = v1;
            } else if (OUTMODE == 3) {
                __half* Cb = (__half*)C_ + (long)z * sC;
                *(__half2*)&Cb[(long)row * N + col] = __floats2half2_rn(v0.x, v0.y);
                *(__half2*)&Cb[(long)(row + 8) * N + col] = __floats2half2_rn(v1.x, v1.y);
            } else {   // 4: half head-split scatter
                __half* C = (__half*)C_;
                int bb = row >> 9, s = row & 511, h = col >> 6, d = col & 63;
                *(__half2*)&C[(((long)(bb * NH_ + h)) * S_ + s) * DH_ + d] =
                    __floats2half2_rn(v0.x, v0.y);
                *(__half2*)&C[(((long)(bb * NH_ + h)) * S_ + s + 8) * DH_ + d] =
                    __floats2half2_rn(v1.x, v1.y);
            }
        }
    }
}

// ---- merged QKV projection: fp16 HMMA; q,k out fp16 head-split; v out f32 ----
struct QKVArgs {
    const __half* A[3];
    const __half* W[3];
    const float* b[3];
    void* C[3];
};
__global__ __launch_bounds__(256, 2) void qkv_hgemm(QKVArgs p)
{
    extern __shared__ unsigned smem_u[];
    const int z = blockIdx.z;
    if (z < 2)
        hgemm_body<128, 4, 3>(p.A[z], p.W[z], p.b[z], p.C[z], HID_, HID_, z, 0, smem_u);
    else
        hgemm_body<128, 1, 3>(p.A[z], p.W[z], p.b[z], p.C[z], HID_, HID_, z, 0, smem_u);
}

// ---- QK scores: fp16 HMMA, batched over z, fp16 linear output ----
__global__ __launch_bounds__(256, 2) void qk_hgemm(
    const __half* __restrict__ A, const __half* __restrict__ Bm,
    __half* __restrict__ C, int N, int K, long sA, long sB, long sC)
{
    extern __shared__ unsigned smem_u[];
    const int z = blockIdx.z;
    hgemm_body<128, 3, 3>(A + (long)z * sA, Bm + (long)z * sB, nullptr, C,
                          N, K, z, sC, smem_u);
}

// ---------------------------------------------------------------------------
// TF32 GEMM body (PV + O-proj only) — exact R9-348 code path.
// AHALF: A fp16 in gmem. OUTMODE 0: f32 linear. 2: AO accumulate f32.
// ---------------------------------------------------------------------------
template<int BN, int BNN, int OUTMODE, int AHALF, int NSTAGE>
__global__ __launch_bounds__(256, 2) void mma_gemm(
    const void* __restrict__ A, const float* __restrict__ Bm,
    const float* __restrict__ bias, void* __restrict__ C_,
    int N, int K, long sA, long sB, long sC)
{
    constexpr int NT8 = BN / 8;
    constexpr int NTW = NT8 / 4;
    constexpr int APACK = 4224;
    constexpr int BPACK = ((((NT8 * 4 - 1) * 33) + 31) * 2 + 2 + 3) & ~3;
    constexpr int RA_BYTES = AHALF ? (128 * 40 * 2) : (128 * 36 * 4);
    constexpr int RB_BYTES = (BNN == 0) ? BN * 36 * 4 : 32 * (BN + 4) * 4;

    extern __shared__ unsigned smem_u[];
    unsigned* sA_ = smem_u;
    unsigned* sB_ = smem_u + APACK;
    char* rawA = (char*)(smem_u + APACK + BPACK);
    char* rawB = rawA + NSTAGE * RA_BYTES;

    const int z = blockIdx.z;
    const float*  Abf = (const float*)A + (AHALF ? 0 : (long)z * sA);
    const __half* Abh = (const __half*)A + (AHALF ? (long)z * sA : 0);
    const float*  Bb = Bm + (long)z * sB;

    const int m0 = blockIdx.y * 128;
    const int n0 = blockIdx.x * BN;
    const int tid = threadIdx.x;
    const int lane = tid & 31;
    const int wid = tid >> 5;
    const int wm = wid & 1;
    const int wn = wid >> 1;

    float acc[4][NTW][4];
#pragma unroll
    for (int mt = 0; mt < 4; mt++)
#pragma unroll
        for (int nt = 0; nt < NTW; nt++)
#pragma unroll
            for (int e = 0; e < 4; e++) acc[mt][nt][e] = 0.f;

    const int nTiles = K >> 5;

    auto loadA = [&](int kt, char* dstA) {
        if (AHALF == 0) {
            float* dA = (float*)dstA;
#pragma unroll
            for (int i = 0; i < 4; i++) {
                int f = tid + i * 256;
                int row = f >> 3, k4 = (f & 7) * 4;
                cpa16(&dA[row * 36 + k4], &Abf[(long)(m0 + row) * K + kt + k4]);
            }
        } else {
            __half* dA = (__half*)dstA;
#pragma unroll
            for (int i = 0; i < 2; i++) {
                int f = tid + i * 256;
                int row = f >> 2, k8 = (f & 3) * 8;
                cpa16(&dA[row * 40 + k8], &Abh[(long)(m0 + row) * K + kt + k8]);
            }
        }
    };
    auto loadB = [&](int kt, char* dstB) {
        float* dB = (float*)dstB;
        if (BNN == 0) {
#pragma unroll
            for (int i = 0; i < BN / 32; i++) {
                int f = tid + i * 256;
                int n = f >> 3, k4 = (f & 7) * 4;
                cpa16(&dB[n * 36 + k4], &Bb[(long)(n0 + n) * K + kt + k4]);
            }
        } else {
#pragma unroll
            for (int i = 0; i < BN / 32; i++) {
                int f = tid + i * 256;
                int k = f / (BN / 4), n4 = (f % (BN / 4)) * 4;
                cpa16(&dB[k * (BN + 4) + n4], &Bb[(long)(kt + k) * N + n0 + n4]);
            }
        }
    };

#pragma unroll
    for (int s = 0; s < NSTAGE - 1; s++) {
        if (s < nTiles) {
            loadA(s * 32, rawA + s * RA_BYTES);
            loadB(s * 32, rawB + s * RB_BYTES);
        }
        CP_COMMIT();
    }

    for (int t = 0; t < nTiles; t++) {
        CP_WAIT(NSTAGE - 2);
        __syncthreads();
        {
            int nx = t + NSTAGE - 1;
            if (nx < nTiles) {
                loadA(nx * 32, rawA + (nx % NSTAGE) * RA_BYTES);
                loadB(nx * 32, rawB + (nx % NSTAGE) * RB_BYTES);
            }
            CP_COMMIT();
        }
        const int cur = t % NSTAGE;

        if (AHALF == 0) {
            const float* rA = (const float*)(rawA + cur * RA_BYTES);
#pragma unroll
            for (int i = 0; i < 4; i++) {
                int f = tid + i * 256;
                int row = f >> 3;
                int k4 = (f & 7) * 4;
                float4 v = *(const float4*)&rA[row * 36 + k4];
                int ks = k4 >> 3;
                int mt = row >> 4, rr = row & 15;
                int regb = ((k4 & 4) ? 2 : 0) + (rr >= 8 ? 1 : 0);
                unsigned* p = &sA_[(((mt * 4 + ks) * 33) + (rr & 7) * 4) * 4 + regb];
                p[0] = f2tf(v.x); p[4] = f2tf(v.y); p[8] = f2tf(v.z); p[12] = f2tf(v.w);
            }
        } else {
            const __half* rA = (const __half*)(rawA + cur * RA_BYTES);
#pragma unroll
            for (int i = 0; i < 2; i++) {
                int f = tid + i * 256;
                int row = f >> 2;
                int k8 = (f & 3) * 8;
                const __half2* hv = (const __half2*)&rA[row * 40 + k8];
                float2 f0 = __half22float2(hv[0]);
                float2 f1 = __half22float2(hv[1]);
                float2 f2 = __half22float2(hv[2]);
                float2 f3 = __half22float2(hv[3]);
                int ks = k8 >> 3;
                int mt = row >> 4, rr = row & 15;
                int rb8 = (rr >= 8 ? 1 : 0);
                unsigned* p = &sA_[(((mt * 4 + ks) * 33) + (rr & 7) * 4) * 4];
                p[rb8 + 0]  = f2tf(f0.x); p[rb8 + 4]  = f2tf(f0.y);
                p[rb8 + 8]  = f2tf(f1.x); p[rb8 + 12] = f2tf(f1.y);
                p[rb8 + 2]  = f2tf(f2.x); p[rb8 + 6]  = f2tf(f2.y);
                p[rb8 + 10] = f2tf(f3.x); p[rb8 + 14] = f2tf(f3.y);
            }
        }
        {
            const float* rB = (const float*)(rawB + cur * RB_BYTES);
            if (BNN == 0) {
#pragma unroll
                for (int i = 0; i < BN / 32; i++) {
                    int f = tid + i * 256;
                    int n = f >> 3;
                    int k4 = (f & 7) * 4;
                    float4 v = *(const float4*)&rB[n * 36 + k4];
                    int ks = k4 >> 3;
                    int reg = (k4 & 4) ? 1 : 0;
                    int nt = n >> 3;
                    unsigned* p = &sB_[(((nt * 4 + ks) * 33) + (n & 7) * 4) * 2 + reg];
                    p[0] = f2tf(v.x); p[2] = f2tf(v.y); p[4] = f2tf(v.z); p[6] = f2tf(v.w);
                }
            } else {
#pragma unroll
                for (int i = 0; i < BN / 32; i++) {
                    int f = tid + i * 256;
                    int k = f / (BN / 4);
                    int n4 = (f % (BN / 4)) * 4;
                    float4 v = *(const float4*)&rB[k * (BN + 4) + n4];
                    int ks = k >> 3, kc = k & 7;
                    int reg = (kc & 4) ? 1 : 0;
                    int nt = n4 >> 3;
                    unsigned* p = &sB_[(((nt * 4 + ks) * 33) + (n4 & 7) * 4 + (kc & 3)) * 2 + reg];
                    p[0] = f2tf(v.x); p[8] = f2tf(v.y); p[16] = f2tf(v.z); p[24] = f2tf(v.w);
                }
            }
        }
        __syncthreads();

#pragma unroll
        for (int ks = 0; ks < 4; ks++) {
            unsigned af[4][4];
            unsigned bf[NTW][2];
#pragma unroll
            for (int mt = 0; mt < 4; mt++) {
                uint4 tt = *(const uint4*)&sA_[((((wm * 4 + mt) * 4 + ks) * 33) + lane) * 4];
                af[mt][0] = tt.x; af[mt][1] = tt.y; af[mt][2] = tt.z; af[mt][3] = tt.w;
            }
#pragma unroll
            for (int nt = 0; nt < NTW; nt++) {
                uint2 tt = *(const uint2*)&sB_[((((wn * NTW + nt) * 4 + ks) * 33) + lane) * 2];
                bf[nt][0] = tt.x; bf[nt][1] = tt.y;
            }
#pragma unroll
            for (int mt = 0; mt < 4; mt++)
#pragma unroll
                for (int nt = 0; nt < NTW; nt++)
                    mma_tf32(acc[mt][nt], af[mt], bf[nt]);
        }
    }

    const int r0 = lane >> 2;
    const int c0l = (lane & 3) * 2;
#pragma unroll
    for (int mt = 0; mt < 4; mt++) {
#pragma unroll
        for (int nt = 0; nt < NTW; nt++) {
            int row = m0 + wm * 64 + mt * 16 + r0;
            int col = n0 + (wn * NTW + nt) * 8 + c0l;
            float2 v0 = make_float2(acc[mt][nt][0], acc[mt][nt][1]);
            float2 v1 = make_float2(acc[mt][nt][2], acc[mt][nt][3]);
            if (bias) {
                float bx = bias[col], by = bias[col + 1];
                v0.x += bx; v0.y += by;
                v1.x += bx; v1.y += by;
            }
            if (OUTMODE == 0) {
                float* Cb = (float*)C_ + (long)z * sC;
                *(float2*)&Cb[(long)row * N + col] = v0;
                *(float2*)&Cb[(long)(row + 8) * N + col] = v1;
            } else {   // 2: AO accumulate
                float* C = (float*)C_;
                int b = z >> 4, h = z & 15;
                float* base = C + ((long)(b * S_ + row)) * HID_ + h * 64 + col;
                float2 o0 = *(float2*)base;
                float2 o1 = *(float2*)(base + 8 * HID_);
                o0.x += v0.x; o0.y += v0.y;
                o1.x += v1.x; o1.y += v1.y;
                *(float2*)base = o0;
                *(float2*)(base + 8 * HID_) = o1;
            }
        }
    }
}

// smem byte sizes
#define GSM_H   ((2112 + 2112) * 4 + 3 * (128 * 40 * 2 + 128 * 40 * 2))   // 78336
#define GSM_PV  ((4224 + 2112) * 4 + 2 * (128 * 40 * 2) + 2 * (32 * 68 * 4))  // 63232
#define GSM_O   ((4224 + 2112) * 4 + 2 * (128 * 36 * 4 + 64 * 36 * 4))        // 80640

// ---------------------------------------------------------------------------
// Fused rel kernel, streaming-softmax (fp16-q variant, measured in R12).
// ---------------------------------------------------------------------------
#define RELP 72
#define SCP  516
#define CHUNK_F (64 * RELP)
#define SMEM_F ((16 * SCP + 16 * RELP + 1024 + 3 * CHUNK_F + 128 + 16 + 4096) * 4)

__global__ __launch_bounds__(256, 2) void rel_fused(
    const __half* __restrict__ qh, const float* __restrict__ rel,
    const float* __restrict__ Kp, __half* __restrict__ sc,
    float* __restrict__ AO)
{
    extern __shared__ float sm[];
    float* s_sc  = sm;
    float* s_qk  = sm + 16 * SCP;
    float* s_kp  = s_qk + 16 * RELP;
    float* s_rel = s_kp + 1024;
    float* s_red = s_rel + 3 * CHUNK_F;
    float* s_inv = s_red + 128;
    __half* s_sch = (__half*)(s_inv + 16);

    const int bi = blockIdx.x;
    const int b = bi >> 9, i = bi & 511;
    const int tid = threadIdx.x;
    const int lane = tid & 31;
    const int wid = tid >> 5;
    const int lg = lane >> 2;
    const int lm = lane & 3;

    const float* relb = rel + ((long)b * S_ * S_ + i) * DH_;
    __half* scb = sc + (((long)(b * NH_)) * S_ + i) * S_;

    const int qh_h = tid >> 4, qh_c = (tid & 15) * 4;
    uint2 qraw = *(const uint2*)(qh + (((long)(b * NH_ + qh_h)) * S_ + i) * DH_ + qh_c);

#pragma unroll
    for (int qq = 0; qq < 4; qq++) {
        int f = tid + qq * 256;
        int h = f >> 6, jv8 = (f & 63) * 8;
        cpa16(&s_sch[h * 512 + jv8], scb + (long)h * (S_ * S_) + jv8);
    }
    cpa16(&s_kp[tid * 4], Kp + tid * 4);
    CP_COMMIT();

#pragma unroll
    for (int c = 0; c < 2; c++) {
#pragma unroll
        for (int qq = 0; qq < 4; qq++) {
            int f = tid + qq * 256;
            int r = f >> 4, c4 = (f & 15) * 4;
            cpa16(&s_rel[c * CHUNK_F + r * RELP + c4],
                  relb + (long)(c * 64 + r) * (S_ * DH_) + c4);
        }
        CP_COMMIT();
    }

    CP_WAIT(2);
    __syncthreads();
    {
        const __half2* qp = (const __half2*)&qraw;
        float2 a0 = __half22float2(qp[0]);
        float2 a1 = __half22float2(qp[1]);
        int base = qh_h * 64 + qh_c;
        s_qk[qh_h * RELP + qh_c + 0] = a0.x * s_kp[base + 0];
        s_qk[qh_h * RELP + qh_c + 1] = a0.y * s_kp[base + 1];
        s_qk[qh_h * RELP + qh_c + 2] = a1.x * s_kp[base + 2];
        s_qk[qh_h * RELP + qh_c + 3] = a1.y * s_kp[base + 3];
    }
    __syncthreads();

    unsigned af[8][4];
#pragma unroll
    for (int ks = 0; ks < 8; ks++) {
        af[ks][0] = f2tf(s_qk[lg * RELP + ks * 8 + lm]);
        af[ks][1] = f2tf(s_qk[(lg + 8) * RELP + ks * 8 + lm]);
        af[ks][2] = f2tf(s_qk[lg * RELP + ks * 8 + 4 + lm]);
        af[ks][3] = f2tf(s_qk[(lg + 8) * RELP + ks * 8 + 4 + lm]);
    }

    float acc2[4] = {0.f, 0.f, 0.f, 0.f};
    float psum_lo = 0.f, psum_hi = 0.f;
    const int d0 = wid * 8;

#pragma unroll
    for (int t = 0; t < 8; t++) {
        if (t < 7) { CP_WAIT(1); } else { CP_WAIT(0); }
        __syncthreads();
        if (t + 2 < 8) {
            int c = t + 2;
            float* dst = s_rel + (c % 3) * CHUNK_F;
#pragma unroll
            for (int qq = 0; qq < 4; qq++) {
                int f = tid + qq * 256;
                int r = f >> 4, c4 = (f & 15) * 4;
                cpa16(&dst[r * RELP + c4],
                      relb + (long)(c * 64 + r) * (S_ * DH_) + c4);
            }
            CP_COMMIT();
        }

        const float* rb_base = s_rel + (t % 3) * CHUNK_F;

        float acc[4] = {0.f, 0.f, 0.f, 0.f};
        const float* rb = rb_base + (wid * 8 + lg) * RELP;
#pragma unroll
        for (int ks = 0; ks < 8; ks++) {
            unsigned bf[2];
            bf[0] = f2tf(rb[ks * 8 + lm]);
            bf[1] = f2tf(rb[ks * 8 + 4 + lm]);
            mma_tf32(acc, af[ks], bf);
        }

        {
            int col = t * 64 + wid * 8 + lm * 2;
            float b00 = __half2float(s_sch[lg * 512 + col]);
            float b01 = __half2float(s_sch[lg * 512 + col + 1]);
            float b10 = __half2float(s_sch[(lg + 8) * 512 + col]);
            float b11 = __half2float(s_sch[(lg + 8) * 512 + col + 1]);
            float e00 = __expf((b00 + acc[0]) * 0.125f);
            float e01 = __expf((b01 + acc[1]) * 0.125f);
            float e10 = __expf((b10 + acc[2]) * 0.125f);
            float e11 = __expf((b11 + acc[3]) * 0.125f);
            s_sc[lg * SCP + col]           = e00;
            s_sc[lg * SCP + col + 1]       = e01;
            s_sc[(lg + 8) * SCP + col]     = e10;
            s_sc[(lg + 8) * SCP + col + 1] = e11;
            psum_lo += e00 + e01;
            psum_hi += e10 + e11;
        }
        __syncthreads();

#pragma unroll
        for (int ks = 0; ks < 8; ks++) {
            unsigned a2f[4], b2f[2];
            a2f[0] = f2tf(s_sc[lg * SCP + t * 64 + ks * 8 + lm]);
            a2f[1] = f2tf(s_sc[(lg + 8) * SCP + t * 64 + ks * 8 + lm]);
            a2f[2] = f2tf(s_sc[lg * SCP + t * 64 + ks * 8 + 4 + lm]);
            a2f[3] = f2tf(s_sc[(lg + 8) * SCP + t * 64 + ks * 8 + 4 + lm]);
            b2f[0] = f2tf(rb_base[(ks * 8 + lm) * RELP + d0 + lg]);
            b2f[1] = f2tf(rb_base[(ks * 8 + 4 + lm) * RELP + d0 + lg]);
            mma_tf32(acc2, a2f, b2f);
        }
    }

    psum_lo += __shfl_xor_sync(0xffffffffu, psum_lo, 1);
    psum_lo += __shfl_xor_sync(0xffffffffu, psum_lo, 2);
    psum_hi += __shfl_xor_sync(0xffffffffu, psum_hi, 1);
    psum_hi += __shfl_xor_sync(0xffffffffu, psum_hi, 2);
    if (lm == 0) {
        s_red[wid * 16 + lg]     = psum_lo;
        s_red[wid * 16 + 8 + lg] = psum_hi;
    }
    __syncthreads();
    if (tid < 16) {
        float s = 0.f;
#pragma unroll
        for (int w = 0; w < 8; w++) s += s_red[w * 16 + tid];
        s_inv[tid] = 1.0f / s;
    }
    __syncthreads();

#pragma unroll
    for (int qq = 0; qq < 8; qq++) {
        int idx = tid + qq * 256;
        int h = idx >> 7, jv = idx & 127;
        float inv = s_inv[h];
        float4 v = *(const float4*)&s_sc[h * SCP + jv * 4];
        __half2 lo = __floats2half2_rn(v.x * inv, v.y * inv);
        __half2 hi = __floats2half2_rn(v.z * inv, v.w * inv);
        uint2 u;
        u.x = *(unsigned*)&lo;
        u.y = *(unsigned*)&hi;
        *(uint2*)(scb + (long)h * (S_ * S_) + jv * 4) = u;
    }

    {
        float i_lo = s_inv[lg], i_hi = s_inv[lg + 8];
        const int dcol = d0 + lm * 2;
        const long obase = ((long)(b * S_ + i)) * HID_;
        float2 o0, o1;
        o0.x = s_kp[lg * 64 + dcol]           * acc2[0] * i_lo;
        o0.y = s_kp[lg * 64 + dcol + 1]       * acc2[1] * i_lo;
        o1.x = s_kp[(lg + 8) * 64 + dcol]     * acc2[2] * i_hi;
        o1.y = s_kp[(lg + 8) * 64 + dcol + 1] * acc2[3] * i_hi;
        *(float2*)&AO[obase + lg * 64 + dcol] = o0;
        *(float2*)&AO[obase + (lg + 8) * 64 + dcol] = o1;
    }
}

// ---------------------------------------------------------------------------
extern "C" void kernel_launch(void* const* d_in, const int* in_sizes, int n_in,
                              void* d_out, int out_size)
{
    const float* key   = (const float*)d_in[0];
    const float* value = (const float*)d_in[1];
    const float* query = (const float*)d_in[2];
    const float* rel   = (const float*)d_in[3];
    const float* Wq = (const float*)d_in[5];
    const float* bq = (const float*)d_in[6];
    const float* Wk = (const float*)d_in[7];
    const float* bk = (const float*)d_in[8];
    const float* Wv = (const float*)d_in[9];
    const float* bv = (const float*)d_in[10];
    const float* Kp = (const float*)d_in[11];
    const float* Wo = (const float*)d_in[12];
    const float* bo = (const float*)d_in[13];
    float* out = (float*)d_out;

    __half *inh_, *wh_, *qh_, *kh_, *sch_;
    float *v_, *ao_;
    cudaGetSymbolAddress((void**)&inh_, g_inh);
    cudaGetSymbolAddress((void**)&wh_, g_wh);
    cudaGetSymbolAddress((void**)&qh_, g_qh);
    cudaGetSymbolAddress((void**)&kh_, g_kh);
    cudaGetSymbolAddress((void**)&v_, g_v);
    cudaGetSymbolAddress((void**)&sch_, g_sch);
    cudaGetSymbolAddress((void**)&ao_, g_ao);

    cudaFuncSetAttribute(rel_fused, cudaFuncAttributeMaxDynamicSharedMemorySize, SMEM_F);
    cudaFuncSetAttribute(qkv_hgemm, cudaFuncAttributeMaxDynamicSharedMemorySize, GSM_H);
    cudaFuncSetAttribute(qk_hgemm,  cudaFuncAttributeMaxDynamicSharedMemorySize, GSM_H);
    cudaFuncSetAttribute(mma_gemm<64, 1, 2, 1, 2>, cudaFuncAttributeMaxDynamicSharedMemorySize, GSM_PV);
    cudaFuncSetAttribute(mma_gemm<64, 0, 0, 0, 2>, cudaFuncAttributeMaxDynamicSharedMemorySize, GSM_O);

    dim3 thr(256);
    const int IN_ELEMS = B_ * S_ * HID_;      // 2M
    const int W_ELEMS  = HID_ * HID_;         // 1M

    // 0) inputs + Wq/Wk/Wv -> fp16
    CvtArgs ca;
    ca.s[0] = query; ca.s[1] = key; ca.s[2] = value;
    ca.s[3] = Wq; ca.s[4] = Wk; ca.s[5] = Wv;
    ca.d[0] = inh_; ca.d[1] = inh_ + IN_ELEMS; ca.d[2] = inh_ + 2 * IN_ELEMS;
    ca.d[3] = wh_; ca.d[4] = wh_ + W_ELEMS; ca.d[5] = wh_ + 2 * W_ELEMS;
    ca.n4[0] = ca.n4[1] = ca.n4[2] = IN_ELEMS / 4;
    ca.n4[3] = ca.n4[4] = ca.n4[5] = W_ELEMS / 4;
    cvt_f2h<<<592, thr>>>(ca);

    // 1) q/k/v projections — native fp16 HMMA; q,k fp16 out; v f32 out
    QKVArgs qa;
    qa.A[0] = inh_;  qa.A[1] = inh_ + IN_ELEMS; qa.A[2] = inh_ + 2 * IN_ELEMS;
    qa.W[0] = wh_;   qa.W[1] = wh_ + W_ELEMS;   qa.W[2] = wh_ + 2 * W_ELEMS;
    qa.b[0] = bq;    qa.b[1] = bk;  qa.b[2] = bv;
    qa.C[0] = qh_;   qa.C[1] = kh_; qa.C[2] = v_;
    qkv_hgemm<<<dim3(8, 16, 3), thr, GSM_H>>>(qa);

    // 2) scores = q @ k^T — native fp16 HMMA, fp16 out
    qk_hgemm<<<dim3(4, 4, 64), thr, GSM_H>>>(
        qh_, kh_, sch_, S_, DH_,
        (long)S_ * DH_, (long)S_ * DH_, (long)S_ * S_);

    // 3) fused rel/softmax (fp16 q)
    rel_fused<<<B_ * S_, thr, SMEM_F>>>(qh_, rel, Kp, sch_, ao_);

    // 4) AO += probs(fp16) @ v(f32) — exact R9 PV config
    mma_gemm<64, 1, 2, 1, 2><<<dim3(1, 4, 64), thr, GSM_PV>>>(
        sch_, v_, nullptr, ao_, DH_, S_,
        (long)S_ * S_, (long)S_ * DH_, 0);

    // 5) final projection — exact R9 f32 config
    mma_gemm<64, 0, 0, 0, 2><<<dim3(16, 16, 1), thr, GSM_O>>>(
        ao_, Wo, bo, out, HID_, HID_, 0, 0, 0);
}

// round 17
// speedup vs baseline: 1.2117x; 1.0065x over previous
#include <cuda_runtime.h>
#include <cuda_fp16.h>
#include <math.h>

#define B_ 4
#define S_ 512
#define HID_ 1024
#define NH_ 16
#define DH_ 64

// Scratch (device globals: allocation-free rule)
__device__ __align__(16) __half g_inh[3 * B_ * S_ * HID_];   // fp16 inputs
__device__ __align__(16) __half g_wh[3 * HID_ * HID_];       // fp16 Wq,Wk,Wv
__device__ __align__(16) __half g_qh[B_ * NH_ * S_ * DH_];   // fp16 q [b,h,s,d]
__device__ __align__(16) __half g_kh[B_ * NH_ * S_ * DH_];   // fp16 k
__device__ __align__(16) float  g_v[B_ * NH_ * S_ * DH_];    // f32 v [b,h,s,d]
__device__ __align__(16) __half g_vt[B_ * NH_ * DH_ * S_];   // fp16 v^T [b,h,d,s]
__device__ __align__(16) __half g_sch[B_ * NH_ * S_ * S_];   // scores -> probs
__device__ __align__(16) float  g_ao[B_ * S_ * HID_];        // [b,i,h*64+d]

__device__ __forceinline__ unsigned f2tf(float x) {
    unsigned u;
    asm("cvt.rna.tf32.f32 %0, %1;" : "=r"(u) : "f"(x));
    return u;
}

__device__ __forceinline__ void mma_tf32(float* c, const unsigned* a, const unsigned* b) {
    asm volatile(
        "mma.sync.aligned.m16n8k8.row.col.f32.tf32.tf32.f32 "
        "{%0,%1,%2,%3}, {%4,%5,%6,%7}, {%8,%9}, {%0,%1,%2,%3};"
        : "+f"(c[0]), "+f"(c[1]), "+f"(c[2]), "+f"(c[3])
        : "r"(a[0]), "r"(a[1]), "r"(a[2]), "r"(a[3]), "r"(b[0]), "r"(b[1]));
}

__device__ __forceinline__ void mma_f16(float* c, const unsigned* a, const unsigned* b) {
    asm volatile(
        "mma.sync.aligned.m16n8k16.row.col.f32.f16.f16.f32 "
        "{%0,%1,%2,%3}, {%4,%5,%6,%7}, {%8,%9}, {%0,%1,%2,%3};"
        : "+f"(c[0]), "+f"(c[1]), "+f"(c[2]), "+f"(c[3])
        : "r"(a[0]), "r"(a[1]), "r"(a[2]), "r"(a[3]), "r"(b[0]), "r"(b[1]));
}

__device__ __forceinline__ unsigned sptr(const void* p) {
    return (unsigned)__cvta_generic_to_shared(p);
}
__device__ __forceinline__ void cpa16(void* dst, const void* src) {
    asm volatile("cp.async.cg.shared.global [%0], [%1], 16;" :: "r"(sptr(dst)), "l"(src));
}
#define CP_COMMIT() asm volatile("cp.async.commit_group;")
#define CP_WAIT(n)  asm volatile("cp.async.wait_group %0;" :: "n"(n))

// ---------------------------------------------------------------------------
// f32 -> fp16 bulk convert: 6 segments (3 inputs, 3 weights)
// ---------------------------------------------------------------------------
struct CvtArgs {
    const float* s[6];
    __half* d[6];
    int n4[6];
};
__global__ __launch_bounds__(256) void cvt_f2h(CvtArgs a)
{
#pragma unroll
    for (int seg = 0; seg < 6; seg++) {
        const float4* s4 = (const float4*)a.s[seg];
        __half2* d2 = (__half2*)a.d[seg];
        int n4 = a.n4[seg];
        for (int i = blockIdx.x * blockDim.x + threadIdx.x; i < n4;
             i += gridDim.x * blockDim.x) {
            float4 v = s4[i];
            d2[i * 2]     = __floats2half2_rn(v.x, v.y);
            d2[i * 2 + 1] = __floats2half2_rn(v.z, v.w);
        }
    }
}

// ---------------------------------------------------------------------------
// v [b,h,s,d] f32 -> vT [b,h,d,s] fp16 (coalesced both sides via smem tile)
// ---------------------------------------------------------------------------
__global__ __launch_bounds__(256) void vt_cvt(const float* __restrict__ v,
                                              __half* __restrict__ vt)
{
    __shared__ float t[64][65];
    const int z = blockIdx.x;                 // b*NH + h
    const float* src = v + (long)z * S_ * DH_;
    __half* dst = vt + (long)z * DH_ * S_;
    const int tid = threadIdx.x;
    for (int tile = 0; tile < 8; tile++) {    // 64 s-rows per tile
        for (int i = tid; i < 4096; i += 256) {
            int s = i >> 6, d = i & 63;
            t[s][d] = src[(long)(tile * 64 + s) * DH_ + d];
        }
        __syncthreads();
        for (int i = tid; i < 4096; i += 256) {
            int d = i >> 6, s = i & 63;
            dst[(long)d * S_ + tile * 64 + s] = __float2half(t[s][d]);
        }
        __syncthreads();
    }
}

// ---------------------------------------------------------------------------
// Native fp16 HMMA GEMM body (m16n8k16). NT: A [M,K], B [N,K], both fp16.
// BM=128, BK=32 (2 k-steps of 16), cp.async ring of NSTAGE.
// OUTMODE 1: f32 head-split scatter. 2: AO accumulate f32 (z = b*16+h).
//         3: half C[row*N+col]+z*sC. 4: half head-split scatter.
// ---------------------------------------------------------------------------
template<int BN, int OUTMODE, int NSTAGE>
__device__ __forceinline__ void hgemm_body(
    const __half* __restrict__ Ab, const __half* __restrict__ Bb,
    const float* __restrict__ bias, void* __restrict__ C_,
    int N, int K, int z, long sC, unsigned* smem_u)
{
    constexpr int NT8 = BN / 8;
    constexpr int NTW = NT8 / 4;
    constexpr int APACK = 2112;                       // u32
    constexpr int BPACK = (BN == 128) ? 2112 : 1056;  // u32
    constexpr int RA_H = 128 * 40;                    // halves / stage
    constexpr int RB_H = BN * 40;

    unsigned* sA_ = smem_u;
    unsigned* sB_ = smem_u + APACK;
    __half* rawA = (__half*)(smem_u + APACK + BPACK);
    __half* rawB = rawA + NSTAGE * RA_H;

    const int m0 = blockIdx.y * 128;
    const int n0 = blockIdx.x * BN;
    const int tid = threadIdx.x;
    const int lane = tid & 31;
    const int wid = tid >> 5;
    const int wm = wid & 1;
    const int wn = wid >> 1;

    float acc[4][NTW][4];
#pragma unroll
    for (int mt = 0; mt < 4; mt++)
#pragma unroll
        for (int nt = 0; nt < NTW; nt++)
#pragma unroll
            for (int e = 0; e < 4; e++) acc[mt][nt][e] = 0.f;

    const int nTiles = K >> 5;

    auto loadA = [&](int kt, __half* dA) {
#pragma unroll
        for (int i = 0; i < 2; i++) {
            int f = tid + i * 256;
            int row = f >> 2, k8 = (f & 3) * 8;
            cpa16(&dA[row * 40 + k8], &Ab[(long)(m0 + row) * K + kt + k8]);
        }
    };
    auto loadB = [&](int kt, __half* dB) {
#pragma unroll
        for (int i = 0; i < BN / 64; i++) {
            int f = tid + i * 256;
            int n = f >> 2, k8 = (f & 3) * 8;
            cpa16(&dB[n * 40 + k8], &Bb[(long)(n0 + n) * K + kt + k8]);
        }
    };

#pragma unroll
    for (int s = 0; s < NSTAGE - 1; s++) {
        if (s < nTiles) {
            loadA(s * 32, rawA + s * RA_H);
            loadB(s * 32, rawB + s * RB_H);
        }
        CP_COMMIT();
    }

    for (int t = 0; t < nTiles; t++) {
        CP_WAIT(NSTAGE - 2);
        __syncthreads();

        {
            int nx = t + NSTAGE - 1;
            if (nx < nTiles) {
                loadA(nx * 32, rawA + (nx % NSTAGE) * RA_H);
                loadB(nx * 32, rawB + (nx % NSTAGE) * RB_H);
            }
            CP_COMMIT();
        }

        const int cur = t % NSTAGE;

        // ---- repack A ----
        {
            const __half* rA = rawA + cur * RA_H;
#pragma unroll
            for (int i = 0; i < 2; i++) {
                int f = tid + i * 256;
                int row = f >> 2;
                int k8 = (f & 3) * 8;
                uint4 hv = *(const uint4*)&rA[row * 40 + k8];
                int kstep = k8 >> 4;
                int hi = (k8 >> 3) & 1;
                int mt = row >> 4, rr = row & 15;
                int regb = hi * 2 + (rr >= 8 ? 1 : 0);
                unsigned* p = &sA_[(((mt * 2 + kstep) * 33) + (rr & 7) * 4) * 4 + regb];
                p[0] = hv.x; p[4] = hv.y; p[8] = hv.z; p[12] = hv.w;
            }
        }
        // ---- repack B ----
        {
            const __half* rB = rawB + cur * RB_H;
#pragma unroll
            for (int i = 0; i < BN / 64; i++) {
                int f = tid + i * 256;
                int n = f >> 2;
                int k8 = (f & 3) * 8;
                uint4 hv = *(const uint4*)&rB[n * 40 + k8];
                int kstep = k8 >> 4;
                int hi = (k8 >> 3) & 1;
                int nt = n >> 3;
                unsigned* p = &sB_[(((nt * 2 + kstep) * 33) + (n & 7) * 4) * 2 + hi];
                p[0] = hv.x; p[2] = hv.y; p[4] = hv.z; p[6] = hv.w;
            }
        }
        __syncthreads();

        // ---- compute: 2 k-steps of m16n8k16 ----
#pragma unroll
        for (int ks = 0; ks < 2; ks++) {
            unsigned af[4][4];
            unsigned bf[NTW][2];
#pragma unroll
            for (int mt = 0; mt < 4; mt++) {
                uint4 tt = *(const uint4*)&sA_[((((wm * 4 + mt) * 2 + ks) * 33) + lane) * 4];
                af[mt][0] = tt.x; af[mt][1] = tt.y; af[mt][2] = tt.z; af[mt][3] = tt.w;
            }
#pragma unroll
            for (int nt = 0; nt < NTW; nt++) {
                uint2 tt = *(const uint2*)&sB_[((((wn * NTW + nt) * 2 + ks) * 33) + lane) * 2];
                bf[nt][0] = tt.x; bf[nt][1] = tt.y;
            }
#pragma unroll
            for (int mt = 0; mt < 4; mt++)
#pragma unroll
                for (int nt = 0; nt < NTW; nt++)
                    mma_f16(acc[mt][nt], af[mt], bf[nt]);
        }
    }

    // ---- epilogue ----
    const int r0 = lane >> 2;
    const int c0l = (lane & 3) * 2;
#pragma unroll
    for (int mt = 0; mt < 4; mt++) {
#pragma unroll
        for (int nt = 0; nt < NTW; nt++) {
            int row = m0 + wm * 64 + mt * 16 + r0;
            int col = n0 + (wn * NTW + nt) * 8 + c0l;
            float2 v0 = make_float2(acc[mt][nt][0], acc[mt][nt][1]);
            float2 v1 = make_float2(acc[mt][nt][2], acc[mt][nt][3]);
            if (bias) {
                float bx = bias[col], by = bias[col + 1];
                v0.x += bx; v0.y += by;
                v1.x += bx; v1.y += by;
            }
            if (OUTMODE == 1) {
                float* C = (float*)C_;
                int bb = row >> 9, s = row & 511, h = col >> 6, d = col & 63;
                *(float2*)&C[(((long)(bb * NH_ + h)) * S_ + s) * DH_ + d] = v0;
                *(float2*)&C[(((long)(bb * NH_ + h)) * S_ + s + 8) * DH_ + d] = v1;
            } else if (OUTMODE == 2) {
                float* C = (float*)C_;
                int b = z >> 4, h = z & 15;
                float* base = C + ((long)(b * S_ + row)) * HID_ + h * 64 + col;
                float2 o0 = *(float2*)base;
                float2 o1 = *(float2*)(base + 8 * HID_);
                o0.x += v0.x; o0.y += v0.y;
                o1.x += v1.x; o1.y += v1.y;
                *(float2*)base = o0;
                *(float2*)(base + 8 * HID_) = o1;
            } else if (OUTMODE == 3) {
                __half* Cb = (__half*)C_ + (long)z * sC;
                *(__half2*)&Cb[(long)row * N + col] = __floats2half2_rn(v0.x, v0.y);
                *(__half2*)&Cb[(long)(row + 8) * N + col] = __floats2half2_rn(v1.x, v1.y);
            } else {   // 4: half head-split scatter
                __half* C = (__half*)C_;
                int bb = row >> 9, s = row & 511, h = col >> 6, d = col & 63;
                *(__half2*)&C[(((long)(bb * NH_ + h)) * S_ + s) * DH_ + d] =
                    __floats2half2_rn(v0.x, v0.y);
                *(__half2*)&C[(((long)(bb * NH_ + h)) * S_ + s + 8) * DH_ + d] =
                    __floats2half2_rn(v1.x, v1.y);
            }
        }
    }
}

// ---- merged QKV projection: fp16 HMMA; q,k out fp16 head-split; v out f32 ----
struct QKVArgs {
    const __half* A[3];
    const __half* W[3];
    const float* b[3];
    void* C[3];
};
__global__ __launch_bounds__(256, 2) void qkv_hgemm(QKVArgs p)
{
    extern __shared__ unsigned smem_u[];
    const int z = blockIdx.z;
    if (z < 2)
        hgemm_body<128, 4, 3>(p.A[z], p.W[z], p.b[z], p.C[z], HID_, HID_, z, 0, smem_u);
    else
        hgemm_body<128, 1, 3>(p.A[z], p.W[z], p.b[z], p.C[z], HID_, HID_, z, 0, smem_u);
}

// ---- QK scores: fp16 HMMA, batched over z, fp16 linear output ----
__global__ __launch_bounds__(256, 2) void qk_hgemm(
    const __half* __restrict__ A, const __half* __restrict__ Bm,
    __half* __restrict__ C, int N, int K, long sA, long sB, long sC)
{
    extern __shared__ unsigned smem_u[];
    const int z = blockIdx.z;
    hgemm_body<128, 3, 3>(A + (long)z * sA, Bm + (long)z * sB, nullptr, C,
                          N, K, z, sC, smem_u);
}

// ---- PV: probs(fp16) @ vT(fp16)^T -> AO accumulate, batched over (b,h) ----
__global__ __launch_bounds__(256, 2) void pv_hgemm(
    const __half* __restrict__ A, const __half* __restrict__ Bm,
    float* __restrict__ C, int N, int K, long sA, long sB)
{
    extern __shared__ unsigned smem_u[];
    const int z = blockIdx.z;
    hgemm_body<64, 2, 3>(A + (long)z * sA, Bm + (long)z * sB, nullptr, C,
                         N, K, z, 0, smem_u);
}

// ---------------------------------------------------------------------------
// TF32 GEMM (O-proj only) — exact R9-348 code path. OUTMODE 0: f32 linear.
// ---------------------------------------------------------------------------
template<int BN, int NSTAGE>
__global__ __launch_bounds__(256, 2) void mma_gemm_o(
    const float* __restrict__ A, const float* __restrict__ Bm,
    const float* __restrict__ bias, float* __restrict__ C,
    int N, int K)
{
    constexpr int NT8 = BN / 8;
    constexpr int NTW = NT8 / 4;
    constexpr int APACK = 4224;
    constexpr int BPACK = ((((NT8 * 4 - 1) * 33) + 31) * 2 + 2 + 3) & ~3;
    constexpr int RA_F = 128 * 36;
    constexpr int RB_F = BN * 36;

    extern __shared__ unsigned smem_u[];
    unsigned* sA_ = smem_u;
    unsigned* sB_ = smem_u + APACK;
    float* rawA = (float*)(smem_u + APACK + BPACK);
    float* rawB = rawA + NSTAGE * RA_F;

    const int m0 = blockIdx.y * 128;
    const int n0 = blockIdx.x * BN;
    const int tid = threadIdx.x;
    const int lane = tid & 31;
    const int wid = tid >> 5;
    const int wm = wid & 1;
    const int wn = wid >> 1;

    float acc[4][NTW][4];
#pragma unroll
    for (int mt = 0; mt < 4; mt++)
#pragma unroll
        for (int nt = 0; nt < NTW; nt++)
#pragma unroll
            for (int e = 0; e < 4; e++) acc[mt][nt][e] = 0.f;

    const int nTiles = K >> 5;

    auto loadA = [&](int kt, float* dA) {
#pragma unroll
        for (int i = 0; i < 4; i++) {
            int f = tid + i * 256;
            int row = f >> 3, k4 = (f & 7) * 4;
            cpa16(&dA[row * 36 + k4], &A[(long)(m0 + row) * K + kt + k4]);
        }
    };
    auto loadB = [&](int kt, float* dB) {
#pragma unroll
        for (int i = 0; i < BN / 32; i++) {
            int f = tid + i * 256;
            int n = f >> 3, k4 = (f & 7) * 4;
            cpa16(&dB[n * 36 + k4], &Bm[(long)(n0 + n) * K + kt + k4]);
        }
    };

#pragma unroll
    for (int s = 0; s < NSTAGE - 1; s++) {
        if (s < nTiles) {
            loadA(s * 32, rawA + s * RA_F);
            loadB(s * 32, rawB + s * RB_F);
        }
        CP_COMMIT();
    }

    for (int t = 0; t < nTiles; t++) {
        CP_WAIT(NSTAGE - 2);
        __syncthreads();
        {
            int nx = t + NSTAGE - 1;
            if (nx < nTiles) {
                loadA(nx * 32, rawA + (nx % NSTAGE) * RA_F);
                loadB(nx * 32, rawB + (nx % NSTAGE) * RB_F);
            }
            CP_COMMIT();
        }
        const int cur = t % NSTAGE;

        {
            const float* rA = rawA + cur * RA_F;
#pragma unroll
            for (int i = 0; i < 4; i++) {
                int f = tid + i * 256;
                int row = f >> 3;
                int k4 = (f & 7) * 4;
                float4 v = *(const float4*)&rA[row * 36 + k4];
                int ks = k4 >> 3;
                int mt = row >> 4, rr = row & 15;
                int regb = ((k4 & 4) ? 2 : 0) + (rr >= 8 ? 1 : 0);
                unsigned* p = &sA_[(((mt * 4 + ks) * 33) + (rr & 7) * 4) * 4 + regb];
                p[0] = f2tf(v.x); p[4] = f2tf(v.y); p[8] = f2tf(v.z); p[12] = f2tf(v.w);
            }
            const float* rB = rawB + cur * RB_F;
#pragma unroll
            for (int i = 0; i < BN / 32; i++) {
                int f = tid + i * 256;
                int n = f >> 3;
                int k4 = (f & 7) * 4;
                float4 v = *(const float4*)&rB[n * 36 + k4];
                int ks = k4 >> 3;
                int reg = (k4 & 4) ? 1 : 0;
                int nt = n >> 3;
                unsigned* p = &sB_[(((nt * 4 + ks) * 33) + (n & 7) * 4) * 2 + reg];
                p[0] = f2tf(v.x); p[2] = f2tf(v.y); p[4] = f2tf(v.z); p[6] = f2tf(v.w);
            }
        }
        __syncthreads();

#pragma unroll
        for (int ks = 0; ks < 4; ks++) {
            unsigned af[4][4];
            unsigned bf[NTW][2];
#pragma unroll
            for (int mt = 0; mt < 4; mt++) {
                uint4 tt = *(const uint4*)&sA_[((((wm * 4 + mt) * 4 + ks) * 33) + lane) * 4];
                af[mt][0] = tt.x; af[mt][1] = tt.y; af[mt][2] = tt.z; af[mt][3] = tt.w;
            }
#pragma unroll
            for (int nt = 0; nt < NTW; nt++) {
                uint2 tt = *(const uint2*)&sB_[((((wn * NTW + nt) * 4 + ks) * 33) + lane) * 2];
                bf[nt][0] = tt.x; bf[nt][1] = tt.y;
            }
#pragma unroll
            for (int mt = 0; mt < 4; mt++)
#pragma unroll
                for (int nt = 0; nt < NTW; nt++)
                    mma_tf32(acc[mt][nt], af[mt], bf[nt]);
        }
    }

    const int r0 = lane >> 2;
    const int c0l = (lane & 3) * 2;
#pragma unroll
    for (int mt = 0; mt < 4; mt++) {
#pragma unroll
        for (int nt = 0; nt < NTW; nt++) {
            int row = m0 + wm * 64 + mt * 16 + r0;
            int col = n0 + (wn * NTW + nt) * 8 + c0l;
            float2 v0 = make_float2(acc[mt][nt][0], acc[mt][nt][1]);
            float2 v1 = make_float2(acc[mt][nt][2], acc[mt][nt][3]);
            float bx = bias[col], by = bias[col + 1];
            v0.x += bx; v0.y += by;
            v1.x += bx; v1.y += by;
            *(float2*)&C[(long)row * N + col] = v0;
            *(float2*)&C[(long)(row + 8) * N + col] = v1;
        }
    }
}

// smem byte sizes
#define GSM_H   ((2112 + 2112) * 4 + 3 * (128 * 40 * 2 + 128 * 40 * 2))   // 78336
#define GSM_PV  ((2112 + 1056) * 4 + 3 * (128 * 40 * 2 + 64 * 40 * 2))    // 58752
#define GSM_O   ((4224 + 2112) * 4 + 2 * (128 * 36 * 4 + 64 * 36 * 4))    // 80640

// ---------------------------------------------------------------------------
// Fused rel kernel, streaming-softmax (fp16-q variant) — unchanged from R16.
// ---------------------------------------------------------------------------
#define RELP 72
#define SCP  516
#define CHUNK_F (64 * RELP)
#define SMEM_F ((16 * SCP + 16 * RELP + 1024 + 3 * CHUNK_F + 128 + 16 + 4096) * 4)

__global__ __launch_bounds__(256, 2) void rel_fused(
    const __half* __restrict__ qh, const float* __restrict__ rel,
    const float* __restrict__ Kp, __half* __restrict__ sc,
    float* __restrict__ AO)
{
    extern __shared__ float sm[];
    float* s_sc  = sm;
    float* s_qk  = sm + 16 * SCP;
    float* s_kp  = s_qk + 16 * RELP;
    float* s_rel = s_kp + 1024;
    float* s_red = s_rel + 3 * CHUNK_F;
    float* s_inv = s_red + 128;
    __half* s_sch = (__half*)(s_inv + 16);

    const int bi = blockIdx.x;
    const int b = bi >> 9, i = bi & 511;
    const int tid = threadIdx.x;
    const int lane = tid & 31;
    const int wid = tid >> 5;
    const int lg = lane >> 2;
    const int lm = lane & 3;

    const float* relb = rel + ((long)b * S_ * S_ + i) * DH_;
    __half* scb = sc + (((long)(b * NH_)) * S_ + i) * S_;

    const int qh_h = tid >> 4, qh_c = (tid & 15) * 4;
    uint2 qraw = *(const uint2*)(qh + (((long)(b * NH_ + qh_h)) * S_ + i) * DH_ + qh_c);

#pragma unroll
    for (int qq = 0; qq < 4; qq++) {
        int f = tid + qq * 256;
        int h = f >> 6, jv8 = (f & 63) * 8;
        cpa16(&s_sch[h * 512 + jv8], scb + (long)h * (S_ * S_) + jv8);
    }
    cpa16(&s_kp[tid * 4], Kp + tid * 4);
    CP_COMMIT();

#pragma unroll
    for (int c = 0; c < 2; c++) {
#pragma unroll
        for (int qq = 0; qq < 4; qq++) {
            int f = tid + qq * 256;
            int r = f >> 4, c4 = (f & 15) * 4;
            cpa16(&s_rel[c * CHUNK_F + r * RELP + c4],
                  relb + (long)(c * 64 + r) * (S_ * DH_) + c4);
        }
        CP_COMMIT();
    }

    CP_WAIT(2);
    __syncthreads();
    {
        const __half2* qp = (const __half2*)&qraw;
        float2 a0 = __half22float2(qp[0]);
        float2 a1 = __half22float2(qp[1]);
        int base = qh_h * 64 + qh_c;
        s_qk[qh_h * RELP + qh_c + 0] = a0.x * s_kp[base + 0];
        s_qk[qh_h * RELP + qh_c + 1] = a0.y * s_kp[base + 1];
        s_qk[qh_h * RELP + qh_c + 2] = a1.x * s_kp[base + 2];
        s_qk[qh_h * RELP + qh_c + 3] = a1.y * s_kp[base + 3];
    }
    __syncthreads();

    unsigned af[8][4];
#pragma unroll
    for (int ks = 0; ks < 8; ks++) {
        af[ks][0] = f2tf(s_qk[lg * RELP + ks * 8 + lm]);
        af[ks][1] = f2tf(s_qk[(lg + 8) * RELP + ks * 8 + lm]);
        af[ks][2] = f2tf(s_qk[lg * RELP + ks * 8 + 4 + lm]);
        af[ks][3] = f2tf(s_qk[(lg + 8) * RELP + ks * 8 + 4 + lm]);
    }

    float acc2[4] = {0.f, 0.f, 0.f, 0.f};
    float psum_lo = 0.f, psum_hi = 0.f;
    const int d0 = wid * 8;

#pragma unroll
    for (int t = 0; t < 8; t++) {
        if (t < 7) { CP_WAIT(1); } else { CP_WAIT(0); }
        __syncthreads();
        if (t + 2 < 8) {
            int c = t + 2;
            float* dst = s_rel + (c % 3) * CHUNK_F;
#pragma unroll
            for (int qq = 0; qq < 4; qq++) {
                int f = tid + qq * 256;
                int r = f >> 4, c4 = (f & 15) * 4;
                cpa16(&dst[r * RELP + c4],
                      relb + (long)(c * 64 + r) * (S_ * DH_) + c4);
            }
            CP_COMMIT();
        }

        const float* rb_base = s_rel + (t % 3) * CHUNK_F;

        float acc[4] = {0.f, 0.f, 0.f, 0.f};
        const float* rb = rb_base + (wid * 8 + lg) * RELP;
#pragma unroll
        for (int ks = 0; ks < 8; ks++) {
            unsigned bf[2];
            bf[0] = f2tf(rb[ks * 8 + lm]);
            bf[1] = f2tf(rb[ks * 8 + 4 + lm]);
            mma_tf32(acc, af[ks], bf);
        }

        {
            int col = t * 64 + wid * 8 + lm * 2;
            float b00 = __half2float(s_sch[lg * 512 + col]);
            float b01 = __half2float(s_sch[lg * 512 + col + 1]);
            float b10 = __half2float(s_sch[(lg + 8) * 512 + col]);
            float b11 = __half2float(s_sch[(lg + 8) * 512 + col + 1]);
            float e00 = __expf((b00 + acc[0]) * 0.125f);
            float e01 = __expf((b01 + acc[1]) * 0.125f);
            float e10 = __expf((b10 + acc[2]) * 0.125f);
            float e11 = __expf((b11 + acc[3]) * 0.125f);
            s_sc[lg * SCP + col]           = e00;
            s_sc[lg * SCP + col + 1]       = e01;
            s_sc[(lg + 8) * SCP + col]     = e10;
            s_sc[(lg + 8) * SCP + col + 1] = e11;
            psum_lo += e00 + e01;
            psum_hi += e10 + e11;
        }
        __syncthreads();

#pragma unroll
        for (int ks = 0; ks < 8; ks++) {
            unsigned a2f[4], b2f[2];
            a2f[0] = f2tf(s_sc[lg * SCP + t * 64 + ks * 8 + lm]);
            a2f[1] = f2tf(s_sc[(lg + 8) * SCP + t * 64 + ks * 8 + lm]);
            a2f[2] = f2tf(s_sc[lg * SCP + t * 64 + ks * 8 + 4 + lm]);
            a2f[3] = f2tf(s_sc[(lg + 8) * SCP + t * 64 + ks * 8 + 4 + lm]);
            b2f[0] = f2tf(rb_base[(ks * 8 + lm) * RELP + d0 + lg]);
            b2f[1] = f2tf(rb_base[(ks * 8 + 4 + lm) * RELP + d0 + lg]);
            mma_tf32(acc2, a2f, b2f);
        }
    }

    psum_lo += __shfl_xor_sync(0xffffffffu, psum_lo, 1);
    psum_lo += __shfl_xor_sync(0xffffffffu, psum_lo, 2);
    psum_hi += __shfl_xor_sync(0xffffffffu, psum_hi, 1);
    psum_hi += __shfl_xor_sync(0xffffffffu, psum_hi, 2);
    if (lm == 0) {
        s_red[wid * 16 + lg]     = psum_lo;
        s_red[wid * 16 + 8 + lg] = psum_hi;
    }
    __syncthreads();
    if (tid < 16) {
        float s = 0.f;
#pragma unroll
        for (int w = 0; w < 8; w++) s += s_red[w * 16 + tid];
        s_inv[tid] = 1.0f / s;
    }
    __syncthreads();

#pragma unroll
    for (int qq = 0; qq < 8; qq++) {
        int idx = tid + qq * 256;
        int h = idx >> 7, jv = idx & 127;
        float inv = s_inv[h];
        float4 v = *(const float4*)&s_sc[h * SCP + jv * 4];
        __half2 lo = __floats2half2_rn(v.x * inv, v.y * inv);
        __half2 hi = __floats2half2_rn(v.z * inv, v.w * inv);
        uint2 u;
        u.x = *(unsigned*)&lo;
        u.y = *(unsigned*)&hi;
        *(uint2*)(scb + (long)h * (S_ * S_) + jv * 4) = u;
    }

    {
        float i_lo = s_inv[lg], i_hi = s_inv[lg + 8];
        const int dcol = d0 + lm * 2;
        const long obase = ((long)(b * S_ + i)) * HID_;
        float2 o0, o1;
        o0.x = s_kp[lg * 64 + dcol]           * acc2[0] * i_lo;
        o0.y = s_kp[lg * 64 + dcol + 1]       * acc2[1] * i_lo;
        o1.x = s_kp[(lg + 8) * 64 + dcol]     * acc2[2] * i_hi;
        o1.y = s_kp[(lg + 8) * 64 + dcol + 1] * acc2[3] * i_hi;
        *(float2*)&AO[obase + lg * 64 + dcol] = o0;
        *(float2*)&AO[obase + (lg + 8) * 64 + dcol] = o1;
    }
}

// ---------------------------------------------------------------------------
extern "C" void kernel_launch(void* const* d_in, const int* in_sizes, int n_in,
                              void* d_out, int out_size)
{
    const float* key   = (const float*)d_in[0];
    const float* value = (const float*)d_in[1];
    const float* query = (const float*)d_in[2];
    const float* rel   = (const float*)d_in[3];
    const float* Wq = (const float*)d_in[5];
    const float* bq = (const float*)d_in[6];
    const float* Wk = (const float*)d_in[7];
    const float* bk = (const float*)d_in[8];
    const float* Wv = (const float*)d_in[9];
    const float* bv = (const float*)d_in[10];
    const float* Kp = (const float*)d_in[11];
    const float* Wo = (const float*)d_in[12];
    const float* bo = (const float*)d_in[13];
    float* out = (float*)d_out;

    __half *inh_, *wh_, *qh_, *kh_, *vt_, *sch_;
    float *v_, *ao_;
    cudaGetSymbolAddress((void**)&inh_, g_inh);
    cudaGetSymbolAddress((void**)&wh_, g_wh);
    cudaGetSymbolAddress((void**)&qh_, g_qh);
    cudaGetSymbolAddress((void**)&kh_, g_kh);
    cudaGetSymbolAddress((void**)&v_, g_v);
    cudaGetSymbolAddress((void**)&vt_, g_vt);
    cudaGetSymbolAddress((void**)&sch_, g_sch);
    cudaGetSymbolAddress((void**)&ao_, g_ao);

    cudaFuncSetAttribute(rel_fused, cudaFuncAttributeMaxDynamicSharedMemorySize, SMEM_F);
    cudaFuncSetAttribute(qkv_hgemm, cudaFuncAttributeMaxDynamicSharedMemorySize, GSM_H);
    cudaFuncSetAttribute(qk_hgemm,  cudaFuncAttributeMaxDynamicSharedMemorySize, GSM_H);
    cudaFuncSetAttribute(pv_hgemm,  cudaFuncAttributeMaxDynamicSharedMemorySize, GSM_PV);
    cudaFuncSetAttribute(mma_gemm_o<64, 2>, cudaFuncAttributeMaxDynamicSharedMemorySize, GSM_O);

    dim3 thr(256);
    const int IN_ELEMS = B_ * S_ * HID_;      // 2M
    const int W_ELEMS  = HID_ * HID_;         // 1M

    // 0) inputs + Wq/Wk/Wv -> fp16
    CvtArgs ca;
    ca.s[0] = query; ca.s[1] = key; ca.s[2] = value;
    ca.s[3] = Wq; ca.s[4] = Wk; ca.s[5] = Wv;
    ca.d[0] = inh_; ca.d[1] = inh_ + IN_ELEMS; ca.d[2] = inh_ + 2 * IN_ELEMS;
    ca.d[3] = wh_; ca.d[4] = wh_ + W_ELEMS; ca.d[5] = wh_ + 2 * W_ELEMS;
    ca.n4[0] = ca.n4[1] = ca.n4[2] = IN_ELEMS / 4;
    ca.n4[3] = ca.n4[4] = ca.n4[5] = W_ELEMS / 4;
    cvt_f2h<<<592, thr>>>(ca);

    // 1) q/k/v projections — fp16 HMMA; q,k fp16 out; v f32 out
    QKVArgs qa;
    qa.A[0] = inh_;  qa.A[1] = inh_ + IN_ELEMS; qa.A[2] = inh_ + 2 * IN_ELEMS;
    qa.W[0] = wh_;   qa.W[1] = wh_ + W_ELEMS;   qa.W[2] = wh_ + 2 * W_ELEMS;
    qa.b[0] = bq;    qa.b[1] = bk;  qa.b[2] = bv;
    qa.C[0] = qh_;   qa.C[1] = kh_; qa.C[2] = v_;
    qkv_hgemm<<<dim3(8, 16, 3), thr, GSM_H>>>(qa);

    // 1b) v [b,h,s,d] f32 -> vT [b,h,d,s] fp16
    vt_cvt<<<B_ * NH_, thr>>>(v_, vt_);

    // 2) scores = q @ k^T — fp16 HMMA, fp16 out
    qk_hgemm<<<dim3(4, 4, 64), thr, GSM_H>>>(
        qh_, kh_, sch_, S_, DH_,
        (long)S_ * DH_, (long)S_ * DH_, (long)S_ * S_);

    // 3) fused rel/softmax (fp16 q)
    rel_fused<<<B_ * S_, thr, SMEM_F>>>(qh_, rel, Kp, sch_, ao_);

    // 4) AO += probs(fp16) @ v — fp16 HMMA NT against vT
    pv_hgemm<<<dim3(1, 4, 64), thr, GSM_PV>>>(
        sch_, vt_, ao_, DH_, S_,
        (long)S_ * S_, (long)DH_ * S_);

    // 5) final projection — tf32 f32 (R9 config)
    mma_gemm_o<64, 2><<<dim3(16, 16, 1), thr, GSM_O>>>(
        ao_, Wo, bo, out, HID_, HID_);
}